// round 13
// baseline (speedup 1.0000x reference)
#include <cuda_runtime.h>
#include <cuda_bf16.h>
#include <math.h>
#include <stdint.h>

#define NPTS  65536
#define DENC  512
#define PDIM  4096
#define TWO_D 1024
#define TWO_P 8192
#define KSPLIT 4

typedef unsigned long long u64;
typedef __nv_bfloat16 bf16;

// Scratch (allocation-free __device__ globals, ~2.42 GB total — links OK)
__device__ bf16  g_eBh [(u64)NPTS * TWO_P];   // 1 GB   eB hi   [n][8192]
__device__ bf16  g_eBl [(u64)NPTS * TWO_P];   // 1 GB   eB lo
__device__ bf16  g_eATh[(u64)TWO_D * NPTS];   // 128 MB eA^T hi [d][65536]
__device__ bf16  g_eATl[(u64)TWO_D * NPTS];   // 128 MB
__device__ bf16  g_C1Th[(u64)TWO_D * TWO_P];  // 16 MB  C1^T hi [d][8192]
__device__ bf16  g_C1Tl[(u64)TWO_D * TWO_P];  // 16 MB
__device__ float g_C1p [(u64)KSPLIT * TWO_D * TWO_P];  // 128 MB split-K partials

// ---------------- PTX helpers (base sm_103 ISA only) ----------------
__device__ __forceinline__ uint32_t smem_u32(const void* p) {
    uint32_t a;
    asm("{ .reg .u64 t; cvta.to.shared.u64 t, %1; cvt.u32.u64 %0, t; }" : "=r"(a) : "l"(p));
    return a;
}
__device__ __forceinline__ void cp_async16(uint32_t dst, const void* src) {
    asm volatile("cp.async.cg.shared.global [%0], [%1], 16;" :: "r"(dst), "l"(src));
}
#define CP_COMMIT() asm volatile("cp.async.commit_group;" ::: "memory")
#define CP_WAIT1()  asm volatile("cp.async.wait_group 1;" ::: "memory")

__device__ __forceinline__ void ldm_x4(uint32_t* r, uint32_t a) {
    asm volatile("ldmatrix.sync.aligned.m8n8.x4.shared.b16 {%0,%1,%2,%3}, [%4];"
        : "=r"(r[0]), "=r"(r[1]), "=r"(r[2]), "=r"(r[3]) : "r"(a));
}
__device__ __forceinline__ void ldm_x4t(uint32_t* r, uint32_t a) {
    asm volatile("ldmatrix.sync.aligned.m8n8.x4.trans.shared.b16 {%0,%1,%2,%3}, [%4];"
        : "=r"(r[0]), "=r"(r[1]), "=r"(r[2]), "=r"(r[3]) : "r"(a));
}
__device__ __forceinline__ void mma16816(float* c, const uint32_t* a, const uint32_t* b) {
    asm volatile("mma.sync.aligned.m16n8k16.row.col.f32.bf16.bf16.f32 "
        "{%0,%1,%2,%3}, {%4,%5,%6,%7}, {%8,%9}, {%0,%1,%2,%3};"
        : "+f"(c[0]), "+f"(c[1]), "+f"(c[2]), "+f"(c[3])
        : "r"(a[0]), "r"(a[1]), "r"(a[2]), "r"(a[3]), "r"(b[0]), "r"(b[1]));
}

// ---------------- fast accurate sincos ----------------
// Cody-Waite 2-term pi/2 reduction + __sinf/__cosf on [-pi/4, pi/4].
__device__ __forceinline__ void fast_sincos(float x, float& s, float& c) {
    float kf = rintf(x * 0.636619772f);          // 2/pi
    int   q  = (int)kf;
    float r  = fmaf(kf, -1.57079637f, x);        // pi/2 hi, exact via fma
    r = fmaf(kf, 4.37113900e-8f, r);             // hi - pi/2 correction
    float sr = __sinf(r), cr = __cosf(r);
    bool  sw = q & 1;
    float s0 = sw ? cr : sr;
    float c0 = sw ? sr : cr;
    s = (q & 2) ? -s0 : s0;
    c = ((q + 1) & 2) ? -c0 : c0;
}

// ---------------- encode ----------------
__device__ __forceinline__ void split_bf16(float v, bf16& h, bf16& l) {
    h = __float2bfloat16(v);
    l = __float2bfloat16(v - __bfloat162float(h));
}

__global__ void enc_eB(const float* __restrict__ pts, const float* __restrict__ W) {
    u64 idx = (u64)blockIdx.x * 256 + threadIdx.x;
    int p = (int)(idx & 4095);
    int n = (int)(idx >> 12);
    float x0 = pts[3*n+0]*20.f, x1 = pts[3*n+1]*20.f, x2 = pts[3*n+2]*20.f;
    float ph = x0*W[p] + x1*W[PDIM+p] + x2*W[2*PDIM+p];
    float s, c; fast_sincos(ph, s, c);
    bf16 ch, cl, sh, sl;
    split_bf16(c, ch, cl); split_bf16(s, sh, sl);
    u64 b = (u64)n * TWO_P;
    g_eBh[b + p] = ch;        g_eBl[b + p] = cl;
    g_eBh[b + PDIM + p] = sh; g_eBl[b + PDIM + p] = sl;
}

__global__ void enc_eAT(const float* __restrict__ pts, const float* __restrict__ W) {
    u64 idx = (u64)blockIdx.x * 256 + threadIdx.x;
    int n = (int)(idx & 65535);
    int j = (int)(idx >> 16);        // 0..511
    float x0 = pts[3*n+0]*20.f, x1 = pts[3*n+1]*20.f, x2 = pts[3*n+2]*20.f;
    float ph = x0*W[j] + x1*W[DENC+j] + x2*W[2*DENC+j];
    float s, c; fast_sincos(ph, s, c);
    bf16 ch, cl, sh, sl;
    split_bf16(c, ch, cl); split_bf16(s, sh, sl);
    g_eATh[(u64)j * NPTS + n] = ch;          g_eATl[(u64)j * NPTS + n] = cl;
    g_eATh[(u64)(j+DENC) * NPTS + n] = sh;   g_eATl[(u64)(j+DENC) * NPTS + n] = sl;
}

// ---------------- mma.sync split-bf16 GEMM, paired-chunk pipeline ----------
// D[m][q] = sum_k A[m][k]*B[q][k], 3 bf16 terms (AhBh + AhBl + AlBh), fp32 acc.
// BM=BN=128, BK=32, 5-stage cp.async ring, prefetch issued 3 chunks ahead,
// ONE wait_group + ONE __syncthreads per TWO chunks. Ring safety: pair kt
// writes slots (kt+3)%5,(kt+4)%5 which never alias read slots kt,kt+1,kt+2.
template<int MODE>
__global__ __launch_bounds__(256, 1)
void gemm_mma(const bf16* __restrict__ Agh, const bf16* __restrict__ Agl,
              const bf16* __restrict__ Bgh, const bf16* __restrict__ Bgl,
              float* __restrict__ outF)
{
    constexpr int  NK   = (MODE == 1) ? (NPTS / KSPLIT / 32) : (TWO_P / 32);
    constexpr u64  LDA  = (MODE == 1) ? (u64)NPTS : (u64)TWO_P;
    constexpr int  BT_B = (MODE == 1) ? 32 * 272 : 128 * 80;   // bytes per B tile (hi)
    constexpr int  STG  = 20480 + 2 * BT_B;                    // bytes per stage
    static_assert(NK % 2 == 0, "paired mainloop needs even NK");

    extern __shared__ __align__(16) char smem[];
    const uint32_t s0 = smem_u32(smem);

    const int tid  = threadIdx.x;
    const int lane = tid & 31;
    const int wid  = tid >> 5;
    const int wr   = wid >> 2;        // 0..1  (m)
    const int wc   = wid & 3;         // 0..3  (n)

    const int m0 = blockIdx.y * 128;
    const int n0 = blockIdx.x * 128;
    const u64 koff = (MODE == 1) ? (u64)blockIdx.z * (NPTS / KSPLIT) : 0;

    const bf16* Ah = Agh + (u64)m0 * LDA + koff;
    const bf16* Al = Agl + (u64)m0 * LDA + koff;
    const bf16* Bh = (MODE == 1) ? (Bgh + n0 + koff * TWO_P) : (Bgh + (u64)n0 * TWO_P);
    const bf16* Bl = (MODE == 1) ? (Bgl + n0 + koff * TWO_P) : (Bgl + (u64)n0 * TWO_P);

#define LOAD_STAGE(SB, KT)                                                     \
    {                                                                          \
        _Pragma("unroll")                                                      \
        for (int p_ = 0; p_ < 2; p_++) {   /* A: 512 chunks of 16B */          \
            int q = tid + p_ * 256;                                            \
            int r = q >> 2, c = q & 3;                                         \
            u64 g = (u64)r * LDA + (u64)(KT) * 32 + c * 8;                     \
            uint32_t d = (SB) + r * 80 + c * 16;                               \
            cp_async16(d,         Ah + g);                                     \
            cp_async16(d + 10240, Al + g);                                     \
        }                                                                      \
        if (MODE == 1) {                   /* B: 32 rows x 256B, n-major */    \
            _Pragma("unroll")                                                  \
            for (int p_ = 0; p_ < 2; p_++) {                                   \
                int q = tid + p_ * 256;                                        \
                int r = q >> 4, c = q & 15;                                    \
                u64 g = (u64)((KT) * 32 + r) * TWO_P + c * 8;                  \
                uint32_t d = (SB) + 20480 + r * 272 + c * 16;                  \
                cp_async16(d,        Bh + g);                                  \
                cp_async16(d + 8704, Bl + g);                                  \
            }                                                                  \
        } else {                           /* B: 128 rows x 64B, K-contig */   \
            _Pragma("unroll")                                                  \
            for (int p_ = 0; p_ < 2; p_++) {                                   \
                int q = tid + p_ * 256;                                        \
                int r = q >> 2, c = q & 3;                                     \
                u64 g = (u64)r * TWO_P + (u64)(KT) * 32 + c * 8;               \
                uint32_t d = (SB) + 20480 + r * 80 + c * 16;                   \
                cp_async16(d,         Bh + g);                                 \
                cp_async16(d + 10240, Bl + g);                                 \
            }                                                                  \
        }                                                                      \
    }

    // per-lane ldmatrix offsets
    const uint32_t aoff = ((lane & 15) + wr * 64) * 80 + (lane >> 4) * 16;
    const uint32_t boff2x = ((lane & 7) + ((lane >> 4) & 1) * 8 + wc * 32) * 80
                          + ((lane >> 3) & 1) * 16;
    const uint32_t boff1x = (lane & 15) * 272 + wc * 64 + ((lane >> 4) & 1) * 16;

#define LDFRAGS(AH, AL, BH, BL, AB, K0)                                        \
    {                                                                          \
        uint32_t Bb_ = (AB) + 20480;                                           \
        _Pragma("unroll")                                                      \
        for (int mi = 0; mi < 4; mi++) {                                       \
            ldm_x4(AH[mi], (AB) + aoff + mi * 1280 + (K0) * 2);                \
            ldm_x4(AL[mi], (AB) + 10240 + aoff + mi * 1280 + (K0) * 2);        \
        }                                                                      \
        _Pragma("unroll")                                                      \
        for (int ni = 0; ni < 4; ni += 2) {                                    \
            if (MODE == 1) {                                                   \
                ldm_x4t(&BH[ni][0], Bb_ + boff1x + ni * 16 + (K0) * 272);      \
                ldm_x4t(&BL[ni][0], Bb_ + 8704 + boff1x + ni * 16 + (K0) * 272);\
            } else {                                                           \
                ldm_x4(&BH[ni][0], Bb_ + boff2x + ni * 640 + (K0) * 2);        \
                ldm_x4(&BL[ni][0], Bb_ + 10240 + boff2x + ni * 640 + (K0) * 2);\
            }                                                                  \
        }                                                                      \
    }

#define DO_HMMA(AH, AL, BH, BL)                                                \
    {                                                                          \
        _Pragma("unroll")                                                      \
        for (int mi = 0; mi < 4; mi++)                                         \
        _Pragma("unroll")                                                      \
        for (int ni = 0; ni < 4; ni++) mma16816(acc[mi][ni], AH[mi], BH[ni]);  \
        _Pragma("unroll")                                                      \
        for (int mi = 0; mi < 4; mi++)                                         \
        _Pragma("unroll")                                                      \
        for (int ni = 0; ni < 4; ni++) mma16816(acc[mi][ni], AH[mi], BL[ni]);  \
        _Pragma("unroll")                                                      \
        for (int mi = 0; mi < 4; mi++)                                         \
        _Pragma("unroll")                                                      \
        for (int ni = 0; ni < 4; ni++) mma16816(acc[mi][ni], AL[mi], BH[ni]);  \
    }

    float acc[4][4][4];
#pragma unroll
    for (int i = 0; i < 4; i++)
#pragma unroll
        for (int j = 0; j < 4; j++)
#pragma unroll
            for (int k = 0; k < 4; k++) acc[i][j][k] = 0.f;

    uint32_t ah0[4][4], al0[4][4], bh0[4][2], bl0[4][2];
    uint32_t ah1[4][4], al1[4][4], bh1[4][2], bl1[4][2];

    // prologue: stages 0,1,2 in flight (groups 0,1,2)
    LOAD_STAGE(s0 + 0 * STG, 0); CP_COMMIT();
    LOAD_STAGE(s0 + 1 * STG, 1); CP_COMMIT();
    LOAD_STAGE(s0 + 2 * STG, 2); CP_COMMIT();
    CP_WAIT1();                      // stages 0,1 landed
    __syncthreads();
    LDFRAGS(ah0, al0, bh0, bl0, s0, 0);          // frags(chunk 0, k0=0)

    int scur = 0;                    // ring slot of chunk kt (kt even)
    for (int kt = 0; kt < NK; kt += 2) {
        const uint32_t Ab0 = s0 + scur * STG;
        int sl1 = scur + 1; if (sl1 == 5) sl1 = 0;
        const uint32_t Ab1 = s0 + sl1 * STG;
        int sl2 = sl1 + 1; if (sl2 == 5) sl2 = 0;
        const uint32_t Ab2 = s0 + sl2 * STG;
        int sw3 = sl2 + 1; if (sw3 == 5) sw3 = 0;  // slot for stage kt+3
        int sw4 = sw3 + 1; if (sw4 == 5) sw4 = 0;  // slot for stage kt+4

        LDFRAGS(ah1, al1, bh1, bl1, Ab0, 16);    // frags(kt, 16)
        DO_HMMA(ah0, al0, bh0, bl0);             // (kt, 0)
        if (kt + 3 < NK) LOAD_STAGE(s0 + sw3 * STG, kt + 3);
        CP_COMMIT();

        LDFRAGS(ah0, al0, bh0, bl0, Ab1, 0);     // frags(kt+1, 0)
        DO_HMMA(ah1, al1, bh1, bl1);             // (kt, 16)

        LDFRAGS(ah1, al1, bh1, bl1, Ab1, 16);    // frags(kt+1, 16)
        DO_HMMA(ah0, al0, bh0, bl0);             // (kt+1, 0)
        if (kt + 4 < NK) LOAD_STAGE(s0 + sw4 * STG, kt + 4);
        CP_COMMIT();

        CP_WAIT1();                              // stages <= kt+3 landed
        __syncthreads();                         // pair barrier
        DO_HMMA(ah1, al1, bh1, bl1);             // (kt+1, 16) — post-barrier issue
        if (kt + 2 < NK) LDFRAGS(ah0, al0, bh0, bl0, Ab2, 0);  // frags(kt+2, 0)

        scur = sl2;
    }

    // ---- epilogue (fp32 out both modes) ----
    const int rbase = wr * 64 + (lane >> 2);
    const int cbase = wc * 32 + (lane & 3) * 2;
    const u64 ldc  = (MODE == 1) ? (u64)TWO_P : (u64)TWO_D;
    float* og = outF + (u64)m0 * ldc + n0
              + ((MODE == 1) ? (u64)blockIdx.z * ((u64)TWO_D * TWO_P) : 0);
#pragma unroll
    for (int mi = 0; mi < 4; mi++)
#pragma unroll
        for (int ni = 0; ni < 4; ni++)
#pragma unroll
            for (int hh = 0; hh < 2; hh++) {
                int r = rbase + mi * 16 + hh * 8;
                int c = cbase + ni * 8;
                *(float2*)&og[(u64)r * ldc + c] =
                    make_float2(acc[mi][ni][hh * 2 + 0], acc[mi][ni][hh * 2 + 1]);
            }
#undef LOAD_STAGE
#undef LDFRAGS
#undef DO_HMMA
}

// ---------------- split-K reduce + bf16 split of C1 ----------------
__global__ void reduce_c1(const float* __restrict__ P,
                          bf16* __restrict__ Th, bf16* __restrict__ Tl)
{
    const u64 CH = (u64)TWO_D * TWO_P;
    u64 i = ((u64)blockIdx.x * 256 + threadIdx.x) * 2;
    float2 a0 = *(const float2*)&P[i];
    float2 a1 = *(const float2*)&P[CH + i];
    float2 a2 = *(const float2*)&P[2 * CH + i];
    float2 a3 = *(const float2*)&P[3 * CH + i];
    float v0 = (a0.x + a1.x) + (a2.x + a3.x);
    float v1 = (a0.y + a1.y) + (a2.y + a3.y);
    bf16 h0, l0, h1, l1;
    split_bf16(v0, h0, l0);
    split_bf16(v1, h1, l1);
    *(__nv_bfloat162*)&Th[i] = __nv_bfloat162(h0, h1);
    *(__nv_bfloat162*)&Tl[i] = __nv_bfloat162(l0, l1);
}

// ---------------- finalize (recomputes eA phases inline) ----------------
__global__ void finalize_kernel(float* __restrict__ G, const float* __restrict__ pts,
                                const float* __restrict__ W)
{
    __shared__ float red[256];
    int n = blockIdx.x, t = threadIdx.x;
    u64 base = (u64)n * TWO_D;
    float x0 = pts[3*n+0]*20.f, x1 = pts[3*n+1]*20.f, x2 = pts[3*n+2]*20.f;

    float re[2], im[2], acc = 0.f;
#pragma unroll
    for (int q = 0; q < 2; q++) {
        int j = t + q * 256;
        float ph = x0*W[j] + x1*W[DENC+j] + x2*W[2*DENC+j];
        float sA, cA; fast_sincos(ph, sA, cA);
        float Gc = G[base + j], Gs = G[base + DENC + j];
        float den = cA * cA + sA * sA;
        float r  = (Gc * cA + Gs * sA) / den;
        float ii = (Gs * cA - Gc * sA) / den;
        re[q] = r; im[q] = ii;
        acc += r * r + ii * ii;
    }
    red[t] = acc;
    __syncthreads();
#pragma unroll
    for (int s = 128; s > 0; s >>= 1) {
        if (t < s) red[t] += red[t + s];
        __syncthreads();
    }
    float scale = 22.62741699796952f / sqrtf(red[0]);   // sqrt(512)/nrm
#pragma unroll
    for (int q = 0; q < 2; q++) {
        int j = t + q * 256;
        G[base + j]        = re[q] * scale;
        G[base + DENC + j] = im[q] * scale;
    }
}

// ---------------------------------------------------------------------------
extern "C" void kernel_launch(void* const* d_in, const int* in_sizes, int n_in,
                              void* d_out, int out_size)
{
    const float* pts = (const float*)d_in[0];
    const float* A   = (const float*)d_in[1];
    const float* B   = (const float*)d_in[2];
    float* out = (float*)d_out;

    bf16 *eBh, *eBl, *eATh, *eATl, *C1Th, *C1Tl;
    float *C1p;
    cudaGetSymbolAddress((void**)&eBh,  g_eBh);
    cudaGetSymbolAddress((void**)&eBl,  g_eBl);
    cudaGetSymbolAddress((void**)&eATh, g_eATh);
    cudaGetSymbolAddress((void**)&eATl, g_eATl);
    cudaGetSymbolAddress((void**)&C1Th, g_C1Th);
    cudaGetSymbolAddress((void**)&C1Tl, g_C1Tl);
    cudaGetSymbolAddress((void**)&C1p,  g_C1p);

    const int SMEM1 = 5 * (20480 + 2 * 32 * 272);    // 189440
    const int SMEM2 = 5 * (20480 + 2 * 128 * 80);    // 204800
    cudaFuncSetAttribute(gemm_mma<1>, cudaFuncAttributeMaxDynamicSharedMemorySize, SMEM1);
    cudaFuncSetAttribute(gemm_mma<2>, cudaFuncAttributeMaxDynamicSharedMemorySize, SMEM2);

    enc_eB <<<((u64)NPTS * PDIM) / 256, 256>>>(pts, B);
    enc_eAT<<<((u64)DENC * NPTS) / 256, 256>>>(pts, A);

    // GEMM1: C1p[z] = partial over K-quarter z of eAT[d][n] * eB[n][p]
    gemm_mma<1><<<dim3(TWO_P / 128, TWO_D / 128, KSPLIT), 256, SMEM1>>>(
        eATh, eATl, eBh, eBl, C1p);
    reduce_c1<<<(TWO_D * TWO_P) / 512, 256>>>(C1p, C1Th, C1Tl);

    // GEMM2: G[n][d] = sum_p eB[n][p] * C1T[d][p]
    gemm_mma<2><<<dim3(TWO_D / 128, NPTS / 128), 256, SMEM2>>>(
        eBh, eBl, C1Th, C1Tl, out);

    finalize_kernel<<<NPTS, 256>>>(out, pts, A);
}

// round 14
// speedup vs baseline: 1.3577x; 1.3577x over previous
#include <cuda_runtime.h>
#include <cuda_fp16.h>
#include <math.h>
#include <stdint.h>

#define NPTS  65536
#define DENC  512
#define PDIM  4096
#define TWO_D 1024
#define TWO_P 8192
#define KSPLIT 4

typedef unsigned long long u64;

// Scratch (allocation-free __device__ globals, ~0.93 GB total)
__device__ half  g_eB16[(u64)NPTS * TWO_P];   // 512 MB eB fp16 [n][8192] (single)
__device__ half  g_eATh[(u64)TWO_D * NPTS];   // 128 MB eA^T hi [d][65536]
__device__ half  g_eATl[(u64)TWO_D * NPTS];   // 128 MB eA^T lo
__device__ half  g_C1Th[(u64)TWO_D * TWO_P];  // 16 MB  C1^T hi [d][8192]
__device__ half  g_C1Tl[(u64)TWO_D * TWO_P];  // 16 MB  C1^T lo
__device__ float g_C1p [(u64)KSPLIT * TWO_D * TWO_P];  // 128 MB split-K partials

// ---------------- PTX helpers (base sm_103 ISA only) ----------------
__device__ __forceinline__ uint32_t smem_u32(const void* p) {
    uint32_t a;
    asm("{ .reg .u64 t; cvta.to.shared.u64 t, %1; cvt.u32.u64 %0, t; }" : "=r"(a) : "l"(p));
    return a;
}
__device__ __forceinline__ void cp_async16(uint32_t dst, const void* src) {
    asm volatile("cp.async.cg.shared.global [%0], [%1], 16;" :: "r"(dst), "l"(src));
}
#define CP_COMMIT() asm volatile("cp.async.commit_group;" ::: "memory")
#define CP_WAIT3()  asm volatile("cp.async.wait_group 3;" ::: "memory")
#define CP_WAIT2()  asm volatile("cp.async.wait_group 2;" ::: "memory")

__device__ __forceinline__ void ldm_x4(uint32_t* r, uint32_t a) {
    asm volatile("ldmatrix.sync.aligned.m8n8.x4.shared.b16 {%0,%1,%2,%3}, [%4];"
        : "=r"(r[0]), "=r"(r[1]), "=r"(r[2]), "=r"(r[3]) : "r"(a));
}
__device__ __forceinline__ void ldm_x4t(uint32_t* r, uint32_t a) {
    asm volatile("ldmatrix.sync.aligned.m8n8.x4.trans.shared.b16 {%0,%1,%2,%3}, [%4];"
        : "=r"(r[0]), "=r"(r[1]), "=r"(r[2]), "=r"(r[3]) : "r"(a));
}
__device__ __forceinline__ void mma16816(float* c, const uint32_t* a, const uint32_t* b) {
    asm volatile("mma.sync.aligned.m16n8k16.row.col.f32.f16.f16.f32 "
        "{%0,%1,%2,%3}, {%4,%5,%6,%7}, {%8,%9}, {%0,%1,%2,%3};"
        : "+f"(c[0]), "+f"(c[1]), "+f"(c[2]), "+f"(c[3])
        : "r"(a[0]), "r"(a[1]), "r"(a[2]), "r"(a[3]), "r"(b[0]), "r"(b[1]));
}

// ---------------- fast accurate sincos ----------------
__device__ __forceinline__ void fast_sincos(float x, float& s, float& c) {
    float kf = rintf(x * 0.636619772f);          // 2/pi
    int   q  = (int)kf;
    float r  = fmaf(kf, -1.57079637f, x);        // pi/2 hi, exact via fma
    r = fmaf(kf, 4.37113900e-8f, r);             // hi - pi/2 correction
    float sr = __sinf(r), cr = __cosf(r);
    bool  sw = q & 1;
    float s0 = sw ? cr : sr;
    float c0 = sw ? sr : cr;
    s = (q & 2) ? -s0 : s0;
    c = ((q + 1) & 2) ? -c0 : c0;
}

// ---------------- encode ----------------
__device__ __forceinline__ void split_f16(float v, half& h, half& l) {
    h = __float2half_rn(v);
    l = __float2half_rn(v - __half2float(h));
}

__global__ void enc_eB(const float* __restrict__ pts, const float* __restrict__ W) {
    u64 idx = (u64)blockIdx.x * 256 + threadIdx.x;
    int p = (int)(idx & 4095);
    int n = (int)(idx >> 12);
    float x0 = pts[3*n+0]*20.f, x1 = pts[3*n+1]*20.f, x2 = pts[3*n+2]*20.f;
    float ph = x0*W[p] + x1*W[PDIM+p] + x2*W[2*PDIM+p];
    float s, c; fast_sincos(ph, s, c);
    u64 b = (u64)n * TWO_P;
    g_eB16[b + p]        = __float2half_rn(c);
    g_eB16[b + PDIM + p] = __float2half_rn(s);
}

__global__ void enc_eAT(const float* __restrict__ pts, const float* __restrict__ W) {
    u64 idx = (u64)blockIdx.x * 256 + threadIdx.x;
    int n = (int)(idx & 65535);
    int j = (int)(idx >> 16);        // 0..511
    float x0 = pts[3*n+0]*20.f, x1 = pts[3*n+1]*20.f, x2 = pts[3*n+2]*20.f;
    float ph = x0*W[j] + x1*W[DENC+j] + x2*W[2*DENC+j];
    float s, c; fast_sincos(ph, s, c);
    half ch, cl, sh, sl;
    split_f16(c, ch, cl); split_f16(s, sh, sl);
    g_eATh[(u64)j * NPTS + n] = ch;          g_eATl[(u64)j * NPTS + n] = cl;
    g_eATh[(u64)(j+DENC) * NPTS + n] = sh;   g_eATl[(u64)(j+DENC) * NPTS + n] = sl;
}

// ---------------- mma.sync one-side-split fp16 GEMM ----------------
// D[m][q] = sum_k A[m][k]*B[q][k], fp32 acc, 2 MMA terms per k-step:
// MODE 1 (GEMM1): A = eAT split (Ah+Al), B = eB single. D = Ah*B + Al*B.
//                 split-K x4 via blockIdx.z, fp32 partials.
// MODE 2 (GEMM2): A = eB single, B = C1T split (Bh+Bl). D = A*Bh + A*Bl.
// BM=BN=128, BK=32, 5-stage cp.async ring, frag double-buffer (R12 mainloop).
template<int MODE>
__global__ __launch_bounds__(256, 1)
void gemm_mma(const half* __restrict__ A0, const half* __restrict__ A1,
              const half* __restrict__ B0, const half* __restrict__ B1,
              float* __restrict__ outF)
{
    constexpr int  NK  = (MODE == 1) ? (NPTS / KSPLIT / 32) : (TWO_P / 32);
    constexpr u64  LDA = (MODE == 1) ? (u64)NPTS : (u64)TWO_P;
    constexpr int  STG = (MODE == 1) ? (2 * 10240 + 8704)    // Ah, Al, B
                                     : (10240 + 2 * 10240);  // A, Bh, Bl

    extern __shared__ __align__(16) char smem[];
    const uint32_t s0 = smem_u32(smem);

    const int tid  = threadIdx.x;
    const int lane = tid & 31;
    const int wid  = tid >> 5;
    const int wr   = wid >> 2;        // 0..1  (m)
    const int wc   = wid & 3;         // 0..3  (n)

    const int m0 = blockIdx.y * 128;
    const int n0 = blockIdx.x * 128;
    const u64 koff = (MODE == 1) ? (u64)blockIdx.z * (NPTS / KSPLIT) : 0;

    const half* Ahp = A0 + (u64)m0 * LDA + koff;
    const half* Alp = (MODE == 1) ? (A1 + (u64)m0 * LDA + koff) : (const half*)0;
    const half* Bhp = (MODE == 1) ? (B0 + n0 + koff * TWO_P) : (B0 + (u64)n0 * TWO_P);
    const half* Blp = (MODE == 2) ? (B1 + (u64)n0 * TWO_P) : (const half*)0;

#define LOAD_STAGE(SB, KT)                                                     \
    {                                                                          \
        _Pragma("unroll")                                                      \
        for (int p_ = 0; p_ < 2; p_++) {   /* A: 512 chunks of 16B */          \
            int q = tid + p_ * 256;                                            \
            int r = q >> 2, c = q & 3;                                         \
            u64 g = (u64)r * LDA + (u64)(KT) * 32 + c * 8;                     \
            uint32_t d = (SB) + r * 80 + c * 16;                               \
            cp_async16(d, Ahp + g);                                            \
            if (MODE == 1) cp_async16(d + 10240, Alp + g);                     \
        }                                                                      \
        if (MODE == 1) {                   /* B: 32 rows x 256B, n-major */    \
            _Pragma("unroll")                                                  \
            for (int p_ = 0; p_ < 2; p_++) {                                   \
                int q = tid + p_ * 256;                                        \
                int r = q >> 4, c = q & 15;                                    \
                u64 g = (u64)((KT) * 32 + r) * TWO_P + c * 8;                  \
                uint32_t d = (SB) + 20480 + r * 272 + c * 16;                  \
                cp_async16(d, Bhp + g);                                        \
            }                                                                  \
        } else {                           /* B: 128 rows x 64B, K-contig */   \
            _Pragma("unroll")                                                  \
            for (int p_ = 0; p_ < 2; p_++) {                                   \
                int q = tid + p_ * 256;                                        \
                int r = q >> 2, c = q & 3;                                     \
                u64 g = (u64)r * TWO_P + (u64)(KT) * 32 + c * 8;               \
                uint32_t d = (SB) + 10240 + r * 80 + c * 16;                   \
                cp_async16(d,         Bhp + g);                                \
                cp_async16(d + 10240, Blp + g);                                \
            }                                                                  \
        }                                                                      \
    }

    // per-lane ldmatrix offsets (layouts validated R8-R12; fp16 == b16)
    const uint32_t aoff = ((lane & 15) + wr * 64) * 80 + (lane >> 4) * 16;
    const uint32_t boff2x = ((lane & 7) + ((lane >> 4) & 1) * 8 + wc * 32) * 80
                          + ((lane >> 3) & 1) * 16;
    const uint32_t boff1x = (lane & 15) * 272 + wc * 64 + ((lane >> 4) & 1) * 16;

#define LDFRAGS(AH, AL, BH, BL, AB, K0)                                        \
    {                                                                          \
        _Pragma("unroll")                                                      \
        for (int mi = 0; mi < 4; mi++) {                                       \
            ldm_x4(AH[mi], (AB) + aoff + mi * 1280 + (K0) * 2);                \
            if (MODE == 1)                                                     \
                ldm_x4(AL[mi], (AB) + 10240 + aoff + mi * 1280 + (K0) * 2);    \
        }                                                                      \
        _Pragma("unroll")                                                      \
        for (int ni = 0; ni < 4; ni += 2) {                                    \
            if (MODE == 1) {                                                   \
                ldm_x4t(&BH[ni][0], (AB) + 20480 + boff1x + ni * 16 + (K0) * 272); \
            } else {                                                           \
                ldm_x4(&BH[ni][0], (AB) + 10240 + boff2x + ni * 640 + (K0) * 2);   \
                ldm_x4(&BL[ni][0], (AB) + 20480 + boff2x + ni * 640 + (K0) * 2);   \
            }                                                                  \
        }                                                                      \
    }

#define DO_HMMA(AH, AL, BH, BL)                                                \
    {                                                                          \
        _Pragma("unroll")                                                      \
        for (int mi = 0; mi < 4; mi++)                                         \
        _Pragma("unroll")                                                      \
        for (int ni = 0; ni < 4; ni++) mma16816(acc[mi][ni], AH[mi], BH[ni]);  \
        if (MODE == 1) {                                                       \
            _Pragma("unroll")                                                  \
            for (int mi = 0; mi < 4; mi++)                                     \
            _Pragma("unroll")                                                  \
            for (int ni = 0; ni < 4; ni++) mma16816(acc[mi][ni], AL[mi], BH[ni]); \
        } else {                                                               \
            _Pragma("unroll")                                                  \
            for (int mi = 0; mi < 4; mi++)                                     \
            _Pragma("unroll")                                                  \
            for (int ni = 0; ni < 4; ni++) mma16816(acc[mi][ni], AH[mi], BL[ni]); \
        }                                                                      \
    }

    float acc[4][4][4];
#pragma unroll
    for (int i = 0; i < 4; i++)
#pragma unroll
        for (int j = 0; j < 4; j++)
#pragma unroll
            for (int k = 0; k < 4; k++) acc[i][j][k] = 0.f;

    uint32_t ah0[4][4], al0[4][4], bh0[4][2], bl0[4][2];
    uint32_t ah1[4][4], al1[4][4], bh1[4][2], bl1[4][2];

    // prologue: stages 0..3 in flight
    LOAD_STAGE(s0 + 0 * STG, 0); CP_COMMIT();
    LOAD_STAGE(s0 + 1 * STG, 1); CP_COMMIT();
    LOAD_STAGE(s0 + 2 * STG, 2); CP_COMMIT();
    LOAD_STAGE(s0 + 3 * STG, 3); CP_COMMIT();
    CP_WAIT3();                      // stage 0 landed
    __syncthreads();
    LDFRAGS(ah0, al0, bh0, bl0, s0, 0);          // frags(chunk 0, k0=0)

    int scur = 0;                    // stage ring index of chunk kt
    for (int kt = 0; kt < NK; kt++) {
        const uint32_t Ab = s0 + scur * STG;
        int snxt = scur + 1; if (snxt == 5) snxt = 0;
        const uint32_t Abn = s0 + snxt * STG;
        int spre = (scur == 0) ? 4 : scur - 1;   // (kt+4) % 5

        LDFRAGS(ah1, al1, bh1, bl1, Ab, 16);     // LSU: frags(kt, k0=16)
        DO_HMMA(ah0, al0, bh0, bl0);             // tensor: frags(kt, k0=0)

        CP_WAIT2();                              // stage kt+1 landed
        __syncthreads();                         // all warps past stage spre reads
        if (kt + 4 < NK) LOAD_STAGE(s0 + spre * STG, kt + 4);
        CP_COMMIT();                             // always: group numbering invariant

        if (kt + 1 < NK) LDFRAGS(ah0, al0, bh0, bl0, Abn, 0);  // frags(kt+1, 0)
        DO_HMMA(ah1, al1, bh1, bl1);             // frags(kt, k0=16)

        scur = snxt;
    }

    // ---- epilogue (fp32 out both modes) ----
    const int rbase = wr * 64 + (lane >> 2);
    const int cbase = wc * 32 + (lane & 3) * 2;
    const u64 ldc  = (MODE == 1) ? (u64)TWO_P : (u64)TWO_D;
    float* og = outF + (u64)m0 * ldc + n0
              + ((MODE == 1) ? (u64)blockIdx.z * ((u64)TWO_D * TWO_P) : 0);
#pragma unroll
    for (int mi = 0; mi < 4; mi++)
#pragma unroll
        for (int ni = 0; ni < 4; ni++)
#pragma unroll
            for (int hh = 0; hh < 2; hh++) {
                int r = rbase + mi * 16 + hh * 8;
                int c = cbase + ni * 8;
                *(float2*)&og[(u64)r * ldc + c] =
                    make_float2(acc[mi][ni][hh * 2 + 0], acc[mi][ni][hh * 2 + 1]);
            }
#undef LOAD_STAGE
#undef LDFRAGS
#undef DO_HMMA
}

// ---------------- split-K reduce + fp16 split of C1 ----------------
__global__ void reduce_c1(const float* __restrict__ P,
                          half* __restrict__ Th, half* __restrict__ Tl)
{
    const u64 CH = (u64)TWO_D * TWO_P;
    u64 i = ((u64)blockIdx.x * 256 + threadIdx.x) * 2;
    float2 a0 = *(const float2*)&P[i];
    float2 a1 = *(const float2*)&P[CH + i];
    float2 a2 = *(const float2*)&P[2 * CH + i];
    float2 a3 = *(const float2*)&P[3 * CH + i];
    float v0 = (a0.x + a1.x) + (a2.x + a3.x);
    float v1 = (a0.y + a1.y) + (a2.y + a3.y);
    half h0, l0, h1, l1;
    split_f16(v0, h0, l0);
    split_f16(v1, h1, l1);
    *(half2*)&Th[i] = __halves2half2(h0, h1);
    *(half2*)&Tl[i] = __halves2half2(l0, l1);
}

// ---------------- finalize (recomputes eA phases inline) ----------------
__global__ void finalize_kernel(float* __restrict__ G, const float* __restrict__ pts,
                                const float* __restrict__ W)
{
    __shared__ float red[256];
    int n = blockIdx.x, t = threadIdx.x;
    u64 base = (u64)n * TWO_D;
    float x0 = pts[3*n+0]*20.f, x1 = pts[3*n+1]*20.f, x2 = pts[3*n+2]*20.f;

    float re[2], im[2], acc = 0.f;
#pragma unroll
    for (int q = 0; q < 2; q++) {
        int j = t + q * 256;
        float ph = x0*W[j] + x1*W[DENC+j] + x2*W[2*DENC+j];
        float sA, cA; fast_sincos(ph, sA, cA);
        float Gc = G[base + j], Gs = G[base + DENC + j];
        float den = cA * cA + sA * sA;
        float r  = (Gc * cA + Gs * sA) / den;
        float ii = (Gs * cA - Gc * sA) / den;
        re[q] = r; im[q] = ii;
        acc += r * r + ii * ii;
    }
    red[t] = acc;
    __syncthreads();
#pragma unroll
    for (int s = 128; s > 0; s >>= 1) {
        if (t < s) red[t] += red[t + s];
        __syncthreads();
    }
    float scale = 22.62741699796952f / sqrtf(red[0]);   // sqrt(512)/nrm
#pragma unroll
    for (int q = 0; q < 2; q++) {
        int j = t + q * 256;
        G[base + j]        = re[q] * scale;
        G[base + DENC + j] = im[q] * scale;
    }
}

// ---------------------------------------------------------------------------
extern "C" void kernel_launch(void* const* d_in, const int* in_sizes, int n_in,
                              void* d_out, int out_size)
{
    const float* pts = (const float*)d_in[0];
    const float* A   = (const float*)d_in[1];
    const float* B   = (const float*)d_in[2];
    float* out = (float*)d_out;

    half *eB16, *eATh, *eATl, *C1Th, *C1Tl;
    float *C1p;
    cudaGetSymbolAddress((void**)&eB16, g_eB16);
    cudaGetSymbolAddress((void**)&eATh, g_eATh);
    cudaGetSymbolAddress((void**)&eATl, g_eATl);
    cudaGetSymbolAddress((void**)&C1Th, g_C1Th);
    cudaGetSymbolAddress((void**)&C1Tl, g_C1Tl);
    cudaGetSymbolAddress((void**)&C1p,  g_C1p);

    const int SMEM1 = 5 * (2 * 10240 + 8704);     // 145920
    const int SMEM2 = 5 * (3 * 10240);            // 153600
    cudaFuncSetAttribute(gemm_mma<1>, cudaFuncAttributeMaxDynamicSharedMemorySize, SMEM1);
    cudaFuncSetAttribute(gemm_mma<2>, cudaFuncAttributeMaxDynamicSharedMemorySize, SMEM2);

    enc_eB <<<((u64)NPTS * PDIM) / 256, 256>>>(pts, B);
    enc_eAT<<<((u64)DENC * NPTS) / 256, 256>>>(pts, A);

    // GEMM1: C1p[z] = partial over K-quarter z of (eATh+eATl)[d][n] * eB16[n][p]
    gemm_mma<1><<<dim3(TWO_P / 128, TWO_D / 128, KSPLIT), 256, SMEM1>>>(
        eATh, eATl, eB16, (half*)0, C1p);
    reduce_c1<<<(TWO_D * TWO_P) / 512, 256>>>(C1p, C1Th, C1Tl);

    // GEMM2: G[n][d] = sum_p eB16[n][p] * (C1Th+C1Tl)[d][p]
    gemm_mma<2><<<dim3(TWO_D / 128, NPTS / 128), 256, SMEM2>>>(
        eB16, (half*)0, C1Th, C1Tl, out);

    finalize_kernel<<<NPTS, 256>>>(out, pts, A);
}

// round 15
// speedup vs baseline: 2.1215x; 1.5626x over previous
#include <cuda_runtime.h>
#include <cuda_fp16.h>
#include <math.h>
#include <stdint.h>

#define NPTS  65536
#define DENC  512
#define PDIM  4096
#define TWO_D 1024
#define TWO_P 8192
#define KSPLIT 4

typedef unsigned long long u64;

// Scratch (allocation-free __device__ globals, ~784 MB total)
__device__ half  g_eB16[(u64)NPTS * TWO_P];   // 512 MB eB  fp16 [n][8192]
__device__ half  g_eAT16[(u64)TWO_D * NPTS];  // 128 MB eA^T fp16 [d][65536]
__device__ half  g_C1T16[(u64)TWO_D * TWO_P]; // 16 MB  C1^T fp16 [d][8192]
__device__ float g_C1p [(u64)KSPLIT * TWO_D * TWO_P];  // 128 MB split-K partials

// ---------------- PTX helpers (base sm_103 ISA only) ----------------
__device__ __forceinline__ uint32_t smem_u32(const void* p) {
    uint32_t a;
    asm("{ .reg .u64 t; cvta.to.shared.u64 t, %1; cvt.u32.u64 %0, t; }" : "=r"(a) : "l"(p));
    return a;
}
__device__ __forceinline__ void cp_async16(uint32_t dst, const void* src) {
    asm volatile("cp.async.cg.shared.global [%0], [%1], 16;" :: "r"(dst), "l"(src));
}
#define CP_COMMIT() asm volatile("cp.async.commit_group;" ::: "memory")
#define CP_WAIT3()  asm volatile("cp.async.wait_group 3;" ::: "memory")
#define CP_WAIT2()  asm volatile("cp.async.wait_group 2;" ::: "memory")

__device__ __forceinline__ void ldm_x4(uint32_t* r, uint32_t a) {
    asm volatile("ldmatrix.sync.aligned.m8n8.x4.shared.b16 {%0,%1,%2,%3}, [%4];"
        : "=r"(r[0]), "=r"(r[1]), "=r"(r[2]), "=r"(r[3]) : "r"(a));
}
__device__ __forceinline__ void ldm_x4t(uint32_t* r, uint32_t a) {
    asm volatile("ldmatrix.sync.aligned.m8n8.x4.trans.shared.b16 {%0,%1,%2,%3}, [%4];"
        : "=r"(r[0]), "=r"(r[1]), "=r"(r[2]), "=r"(r[3]) : "r"(a));
}
__device__ __forceinline__ void mma16816(float* c, const uint32_t* a, const uint32_t* b) {
    asm volatile("mma.sync.aligned.m16n8k16.row.col.f32.f16.f16.f32 "
        "{%0,%1,%2,%3}, {%4,%5,%6,%7}, {%8,%9}, {%0,%1,%2,%3};"
        : "+f"(c[0]), "+f"(c[1]), "+f"(c[2]), "+f"(c[3])
        : "r"(a[0]), "r"(a[1]), "r"(a[2]), "r"(a[3]), "r"(b[0]), "r"(b[1]));
}

// ---------------- fast accurate sincos ----------------
__device__ __forceinline__ void fast_sincos(float x, float& s, float& c) {
    float kf = rintf(x * 0.636619772f);          // 2/pi
    int   q  = (int)kf;
    float r  = fmaf(kf, -1.57079637f, x);        // pi/2 hi, exact via fma
    r = fmaf(kf, 4.37113900e-8f, r);             // hi - pi/2 correction
    float sr = __sinf(r), cr = __cosf(r);
    bool  sw = q & 1;
    float s0 = sw ? cr : sr;
    float c0 = sw ? sr : cr;
    s = (q & 2) ? -s0 : s0;
    c = ((q + 1) & 2) ? -c0 : c0;
}

// ---------------- encode ----------------
__global__ void enc_eB(const float* __restrict__ pts, const float* __restrict__ W) {
    u64 idx = (u64)blockIdx.x * 256 + threadIdx.x;
    int p = (int)(idx & 4095);
    int n = (int)(idx >> 12);
    float x0 = pts[3*n+0]*20.f, x1 = pts[3*n+1]*20.f, x2 = pts[3*n+2]*20.f;
    float ph = x0*W[p] + x1*W[PDIM+p] + x2*W[2*PDIM+p];
    float s, c; fast_sincos(ph, s, c);
    u64 b = (u64)n * TWO_P;
    g_eB16[b + p]        = __float2half_rn(c);
    g_eB16[b + PDIM + p] = __float2half_rn(s);
}

__global__ void enc_eAT(const float* __restrict__ pts, const float* __restrict__ W) {
    u64 idx = (u64)blockIdx.x * 256 + threadIdx.x;
    int n = (int)(idx & 65535);
    int j = (int)(idx >> 16);        // 0..511
    float x0 = pts[3*n+0]*20.f, x1 = pts[3*n+1]*20.f, x2 = pts[3*n+2]*20.f;
    float ph = x0*W[j] + x1*W[DENC+j] + x2*W[2*DENC+j];
    float s, c; fast_sincos(ph, s, c);
    g_eAT16[(u64)j * NPTS + n]          = __float2half_rn(c);
    g_eAT16[(u64)(j+DENC) * NPTS + n]   = __float2half_rn(s);
}

// ---------------- mma.sync single-term fp16 GEMM ----------------
// D[m][q] = sum_k A[m][k]*B[q][k], fp32 acc, 1 HMMA term per k-step.
// MODE 1 (GEMM1): A = eAT [d][n], B = eB [n][p] n-major (ldmatrix.x4.trans),
//                 split-K x4 via blockIdx.z, fp32 partials.
// MODE 2 (GEMM2): A = eB [n][p], B = C1T [d][p] K-contig (ldmatrix.x4).
// BM=BN=128, BK=32, 5-stage cp.async ring, frag double-buffer (R12 mainloop).
template<int MODE>
__global__ __launch_bounds__(256, 1)
void gemm_mma(const half* __restrict__ A0, const half* __restrict__ B0,
              float* __restrict__ outF)
{
    constexpr int  NK  = (MODE == 1) ? (NPTS / KSPLIT / 32) : (TWO_P / 32);
    constexpr u64  LDA = (MODE == 1) ? (u64)NPTS : (u64)TWO_P;
    constexpr int  STG = (MODE == 1) ? (10240 + 8704) : (10240 + 10240);

    extern __shared__ __align__(16) char smem[];
    const uint32_t s0 = smem_u32(smem);

    const int tid  = threadIdx.x;
    const int lane = tid & 31;
    const int wid  = tid >> 5;
    const int wr   = wid >> 2;        // 0..1  (m)
    const int wc   = wid & 3;         // 0..3  (n)

    const int m0 = blockIdx.y * 128;
    const int n0 = blockIdx.x * 128;
    const u64 koff = (MODE == 1) ? (u64)blockIdx.z * (NPTS / KSPLIT) : 0;

    const half* Ap = A0 + (u64)m0 * LDA + koff;
    const half* Bp = (MODE == 1) ? (B0 + n0 + koff * TWO_P) : (B0 + (u64)n0 * TWO_P);

#define LOAD_STAGE(SB, KT)                                                     \
    {                                                                          \
        _Pragma("unroll")                                                      \
        for (int p_ = 0; p_ < 2; p_++) {   /* A: 512 chunks of 16B */          \
            int q = tid + p_ * 256;                                            \
            int r = q >> 2, c = q & 3;                                         \
            u64 g = (u64)r * LDA + (u64)(KT) * 32 + c * 8;                     \
            cp_async16((SB) + r * 80 + c * 16, Ap + g);                        \
        }                                                                      \
        if (MODE == 1) {                   /* B: 32 rows x 256B, n-major */    \
            _Pragma("unroll")                                                  \
            for (int p_ = 0; p_ < 2; p_++) {                                   \
                int q = tid + p_ * 256;                                        \
                int r = q >> 4, c = q & 15;                                    \
                u64 g = (u64)((KT) * 32 + r) * TWO_P + c * 8;                  \
                cp_async16((SB) + 10240 + r * 272 + c * 16, Bp + g);           \
            }                                                                  \
        } else {                           /* B: 128 rows x 64B, K-contig */   \
            _Pragma("unroll")                                                  \
            for (int p_ = 0; p_ < 2; p_++) {                                   \
                int q = tid + p_ * 256;                                        \
                int r = q >> 2, c = q & 3;                                     \
                u64 g = (u64)r * TWO_P + (u64)(KT) * 32 + c * 8;               \
                cp_async16((SB) + 10240 + r * 80 + c * 16, Bp + g);            \
            }                                                                  \
        }                                                                      \
    }

    // per-lane ldmatrix offsets (layouts validated R8-R14)
    const uint32_t aoff = ((lane & 15) + wr * 64) * 80 + (lane >> 4) * 16;
    const uint32_t boff2x = ((lane & 7) + ((lane >> 4) & 1) * 8 + wc * 32) * 80
                          + ((lane >> 3) & 1) * 16;
    const uint32_t boff1x = (lane & 15) * 272 + wc * 64 + ((lane >> 4) & 1) * 16;

#define LDFRAGS(AH, BH, AB, K0)                                                \
    {                                                                          \
        _Pragma("unroll")                                                      \
        for (int mi = 0; mi < 4; mi++)                                         \
            ldm_x4(AH[mi], (AB) + aoff + mi * 1280 + (K0) * 2);                \
        _Pragma("unroll")                                                      \
        for (int ni = 0; ni < 4; ni += 2) {                                    \
            if (MODE == 1) {                                                   \
                ldm_x4t(&BH[ni][0], (AB) + 10240 + boff1x + ni * 16 + (K0) * 272); \
            } else {                                                           \
                ldm_x4(&BH[ni][0], (AB) + 10240 + boff2x + ni * 640 + (K0) * 2);   \
            }                                                                  \
        }                                                                      \
    }

#define DO_HMMA(AH, BH)                                                        \
    {                                                                          \
        _Pragma("unroll")                                                      \
        for (int mi = 0; mi < 4; mi++)                                         \
        _Pragma("unroll")                                                      \
        for (int ni = 0; ni < 4; ni++) mma16816(acc[mi][ni], AH[mi], BH[ni]);  \
    }

    float acc[4][4][4];
#pragma unroll
    for (int i = 0; i < 4; i++)
#pragma unroll
        for (int j = 0; j < 4; j++)
#pragma unroll
            for (int k = 0; k < 4; k++) acc[i][j][k] = 0.f;

    uint32_t ah0[4][4], bh0[4][2];
    uint32_t ah1[4][4], bh1[4][2];

    // prologue: stages 0..3 in flight
    LOAD_STAGE(s0 + 0 * STG, 0); CP_COMMIT();
    LOAD_STAGE(s0 + 1 * STG, 1); CP_COMMIT();
    LOAD_STAGE(s0 + 2 * STG, 2); CP_COMMIT();
    LOAD_STAGE(s0 + 3 * STG, 3); CP_COMMIT();
    CP_WAIT3();                      // stage 0 landed
    __syncthreads();
    LDFRAGS(ah0, bh0, s0, 0);        // frags(chunk 0, k0=0)

    int scur = 0;                    // stage ring index of chunk kt
    for (int kt = 0; kt < NK; kt++) {
        const uint32_t Ab = s0 + scur * STG;
        int snxt = scur + 1; if (snxt == 5) snxt = 0;
        const uint32_t Abn = s0 + snxt * STG;
        int spre = (scur == 0) ? 4 : scur - 1;   // (kt+4) % 5

        LDFRAGS(ah1, bh1, Ab, 16);               // LSU: frags(kt, k0=16)
        DO_HMMA(ah0, bh0);                       // tensor: frags(kt, k0=0)

        CP_WAIT2();                              // stage kt+1 landed
        __syncthreads();                         // all warps past stage spre reads
        if (kt + 4 < NK) LOAD_STAGE(s0 + spre * STG, kt + 4);
        CP_COMMIT();                             // always: group numbering invariant

        if (kt + 1 < NK) LDFRAGS(ah0, bh0, Abn, 0);   // frags(kt+1, 0)
        DO_HMMA(ah1, bh1);                       // frags(kt, k0=16)

        scur = snxt;
    }

    // ---- epilogue (fp32 out both modes) ----
    const int rbase = wr * 64 + (lane >> 2);
    const int cbase = wc * 32 + (lane & 3) * 2;
    const u64 ldc  = (MODE == 1) ? (u64)TWO_P : (u64)TWO_D;
    float* og = outF + (u64)m0 * ldc + n0
              + ((MODE == 1) ? (u64)blockIdx.z * ((u64)TWO_D * TWO_P) : 0);
#pragma unroll
    for (int mi = 0; mi < 4; mi++)
#pragma unroll
        for (int ni = 0; ni < 4; ni++)
#pragma unroll
            for (int hh = 0; hh < 2; hh++) {
                int r = rbase + mi * 16 + hh * 8;
                int c = cbase + ni * 8;
                *(float2*)&og[(u64)r * ldc + c] =
                    make_float2(acc[mi][ni][hh * 2 + 0], acc[mi][ni][hh * 2 + 1]);
            }
#undef LOAD_STAGE
#undef LDFRAGS
#undef DO_HMMA
}

// ---------------- split-K reduce -> fp16 C1T ----------------
__global__ void reduce_c1(const float* __restrict__ P, half* __restrict__ T)
{
    const u64 CH = (u64)TWO_D * TWO_P;
    u64 i = ((u64)blockIdx.x * 256 + threadIdx.x) * 2;
    float2 a0 = *(const float2*)&P[i];
    float2 a1 = *(const float2*)&P[CH + i];
    float2 a2 = *(const float2*)&P[2 * CH + i];
    float2 a3 = *(const float2*)&P[3 * CH + i];
    float v0 = (a0.x + a1.x) + (a2.x + a3.x);
    float v1 = (a0.y + a1.y) + (a2.y + a3.y);
    *(half2*)&T[i] = __halves2half2(__float2half_rn(v0), __float2half_rn(v1));
}

// ---------------- finalize (recomputes eA phases inline) ----------------
__global__ void finalize_kernel(float* __restrict__ G, const float* __restrict__ pts,
                                const float* __restrict__ W)
{
    __shared__ float red[256];
    int n = blockIdx.x, t = threadIdx.x;
    u64 base = (u64)n * TWO_D;
    float x0 = pts[3*n+0]*20.f, x1 = pts[3*n+1]*20.f, x2 = pts[3*n+2]*20.f;

    float re[2], im[2], acc = 0.f;
#pragma unroll
    for (int q = 0; q < 2; q++) {
        int j = t + q * 256;
        float ph = x0*W[j] + x1*W[DENC+j] + x2*W[2*DENC+j];
        float sA, cA; fast_sincos(ph, sA, cA);
        float Gc = G[base + j], Gs = G[base + DENC + j];
        float den = cA * cA + sA * sA;
        float r  = (Gc * cA + Gs * sA) / den;
        float ii = (Gs * cA - Gc * sA) / den;
        re[q] = r; im[q] = ii;
        acc += r * r + ii * ii;
    }
    red[t] = acc;
    __syncthreads();
#pragma unroll
    for (int s = 128; s > 0; s >>= 1) {
        if (t < s) red[t] += red[t + s];
        __syncthreads();
    }
    float scale = 22.62741699796952f / sqrtf(red[0]);   // sqrt(512)/nrm
#pragma unroll
    for (int q = 0; q < 2; q++) {
        int j = t + q * 256;
        G[base + j]        = re[q] * scale;
        G[base + DENC + j] = im[q] * scale;
    }
}

// ---------------------------------------------------------------------------
extern "C" void kernel_launch(void* const* d_in, const int* in_sizes, int n_in,
                              void* d_out, int out_size)
{
    const float* pts = (const float*)d_in[0];
    const float* A   = (const float*)d_in[1];
    const float* B   = (const float*)d_in[2];
    float* out = (float*)d_out;

    half *eB16, *eAT16, *C1T16;
    float *C1p;
    cudaGetSymbolAddress((void**)&eB16,  g_eB16);
    cudaGetSymbolAddress((void**)&eAT16, g_eAT16);
    cudaGetSymbolAddress((void**)&C1T16, g_C1T16);
    cudaGetSymbolAddress((void**)&C1p,   g_C1p);

    const int SMEM1 = 5 * (10240 + 8704);     // 94720
    const int SMEM2 = 5 * (10240 + 10240);    // 102400
    cudaFuncSetAttribute(gemm_mma<1>, cudaFuncAttributeMaxDynamicSharedMemorySize, SMEM1);
    cudaFuncSetAttribute(gemm_mma<2>, cudaFuncAttributeMaxDynamicSharedMemorySize, SMEM2);

    enc_eB <<<((u64)NPTS * PDIM) / 256, 256>>>(pts, B);
    enc_eAT<<<((u64)DENC * NPTS) / 256, 256>>>(pts, A);

    // GEMM1: C1p[z] = partial over K-quarter z of eAT16[d][n] * eB16[n][p]
    gemm_mma<1><<<dim3(TWO_P / 128, TWO_D / 128, KSPLIT), 256, SMEM1>>>(
        eAT16, eB16, C1p);
    reduce_c1<<<(TWO_D * TWO_P) / 512, 256>>>(C1p, C1T16);

    // GEMM2: G[n][d] = sum_p eB16[n][p] * C1T16[d][p]
    gemm_mma<2><<<dim3(TWO_D / 128, NPTS / 128), 256, SMEM2>>>(
        eB16, C1T16, out);

    finalize_kernel<<<NPTS, 256>>>(out, pts, A);
}

// round 16
// speedup vs baseline: 2.1337x; 1.0057x over previous
#include <cuda_runtime.h>
#include <cuda_fp16.h>
#include <math.h>
#include <stdint.h>

#define NPTS  65536
#define DENC  512
#define PDIM  4096
#define TWO_D 1024
#define TWO_P 8192
#define KSPLIT 4

typedef unsigned long long u64;

// Scratch (allocation-free __device__ globals, ~784 MB total)
__device__ half  g_eB16[(u64)NPTS * TWO_P];   // 512 MB eB  fp16 [n][8192]
__device__ half  g_eAT16[(u64)TWO_D * NPTS];  // 128 MB eA^T fp16 [d][65536]
__device__ half  g_C1T16[(u64)TWO_D * TWO_P]; // 16 MB  C1^T fp16 [d][8192]
__device__ float g_C1p [(u64)KSPLIT * TWO_D * TWO_P];  // 128 MB split-K partials

// ---------------- PTX helpers (base sm_103 ISA only) ----------------
__device__ __forceinline__ uint32_t smem_u32(const void* p) {
    uint32_t a;
    asm("{ .reg .u64 t; cvta.to.shared.u64 t, %1; cvt.u32.u64 %0, t; }" : "=r"(a) : "l"(p));
    return a;
}
__device__ __forceinline__ void cp_async16(uint32_t dst, const void* src) {
    asm volatile("cp.async.cg.shared.global [%0], [%1], 16;" :: "r"(dst), "l"(src));
}
#define CP_COMMIT() asm volatile("cp.async.commit_group;" ::: "memory")
#define CP_WAIT3()  asm volatile("cp.async.wait_group 3;" ::: "memory")
#define CP_WAIT2()  asm volatile("cp.async.wait_group 2;" ::: "memory")

__device__ __forceinline__ void ldm_x4(uint32_t* r, uint32_t a) {
    asm volatile("ldmatrix.sync.aligned.m8n8.x4.shared.b16 {%0,%1,%2,%3}, [%4];"
        : "=r"(r[0]), "=r"(r[1]), "=r"(r[2]), "=r"(r[3]) : "r"(a));
}
__device__ __forceinline__ void ldm_x4t(uint32_t* r, uint32_t a) {
    asm volatile("ldmatrix.sync.aligned.m8n8.x4.trans.shared.b16 {%0,%1,%2,%3}, [%4];"
        : "=r"(r[0]), "=r"(r[1]), "=r"(r[2]), "=r"(r[3]) : "r"(a));
}
__device__ __forceinline__ void mma16816(float* c, const uint32_t* a, const uint32_t* b) {
    asm volatile("mma.sync.aligned.m16n8k16.row.col.f32.f16.f16.f32 "
        "{%0,%1,%2,%3}, {%4,%5,%6,%7}, {%8,%9}, {%0,%1,%2,%3};"
        : "+f"(c[0]), "+f"(c[1]), "+f"(c[2]), "+f"(c[3])
        : "r"(a[0]), "r"(a[1]), "r"(a[2]), "r"(a[3]), "r"(b[0]), "r"(b[1]));
}

// ---------------- fast accurate sincos ----------------
__device__ __forceinline__ void fast_sincos(float x, float& s, float& c) {
    float kf = rintf(x * 0.636619772f);          // 2/pi
    int   q  = (int)kf;
    float r  = fmaf(kf, -1.57079637f, x);        // pi/2 hi, exact via fma
    r = fmaf(kf, 4.37113900e-8f, r);             // hi - pi/2 correction
    float sr = __sinf(r), cr = __cosf(r);
    bool  sw = q & 1;
    float s0 = sw ? cr : sr;
    float c0 = sw ? sr : cr;
    s = (q & 2) ? -s0 : s0;
    c = ((q + 1) & 2) ? -c0 : c0;
}

// ---------------- encode ----------------
__global__ void enc_eB(const float* __restrict__ pts, const float* __restrict__ W) {
    u64 idx = (u64)blockIdx.x * 256 + threadIdx.x;
    int p = (int)(idx & 4095);
    int n = (int)(idx >> 12);
    float x0 = pts[3*n+0]*20.f, x1 = pts[3*n+1]*20.f, x2 = pts[3*n+2]*20.f;
    float ph = x0*W[p] + x1*W[PDIM+p] + x2*W[2*PDIM+p];
    float s, c; fast_sincos(ph, s, c);
    u64 b = (u64)n * TWO_P;
    g_eB16[b + p]        = __float2half_rn(c);
    g_eB16[b + PDIM + p] = __float2half_rn(s);
}

__global__ void enc_eAT(const float* __restrict__ pts, const float* __restrict__ W) {
    u64 idx = (u64)blockIdx.x * 256 + threadIdx.x;
    int n = (int)(idx & 65535);
    int j = (int)(idx >> 16);        // 0..511
    float x0 = pts[3*n+0]*20.f, x1 = pts[3*n+1]*20.f, x2 = pts[3*n+2]*20.f;
    float ph = x0*W[j] + x1*W[DENC+j] + x2*W[2*DENC+j];
    float s, c; fast_sincos(ph, s, c);
    g_eAT16[(u64)j * NPTS + n]          = __float2half_rn(c);
    g_eAT16[(u64)(j+DENC) * NPTS + n]   = __float2half_rn(s);
}

// ---------------- mma.sync single-term fp16 GEMM ----------------
// D[m][q] = sum_k A[m][k]*B[q][k], fp32 acc, 1 HMMA term per k-step.
// MODE 1 (GEMM1): A = eAT [d][n], B = eB [n][p] n-major (ldmatrix.x4.trans),
//                 split-K x4 via blockIdx.z, fp32 partials.
//                 Grid: x = d-tile (8, fastest) so concurrent CTAs share each
//                 eB B-slab in L2 (DRAM ~6 GB -> ~0.8 GB); y = p-tile (64).
// MODE 2 (GEMM2): A = eB [n][p], B = C1T [d][p] K-contig (ldmatrix.x4).
//                 Grid: x = d-tile (8, fastest) shares eB A-slab across x.
// BM=BN=128, BK=32, 5-stage cp.async ring, frag double-buffer (R12 mainloop).
template<int MODE>
__global__ __launch_bounds__(256, 1)
void gemm_mma(const half* __restrict__ A0, const half* __restrict__ B0,
              float* __restrict__ outF)
{
    constexpr int  NK  = (MODE == 1) ? (NPTS / KSPLIT / 32) : (TWO_P / 32);
    constexpr u64  LDA = (MODE == 1) ? (u64)NPTS : (u64)TWO_P;
    constexpr int  STG = (MODE == 1) ? (10240 + 8704) : (10240 + 10240);

    extern __shared__ __align__(16) char smem[];
    const uint32_t s0 = smem_u32(smem);

    const int tid  = threadIdx.x;
    const int lane = tid & 31;
    const int wid  = tid >> 5;
    const int wr   = wid >> 2;        // 0..1  (m)
    const int wc   = wid & 3;         // 0..3  (n)

    // MODE 1: x = m-tile (d), y = n-tile (p).  MODE 2: x = n-tile (d), y = m-tile (n).
    const int m0 = ((MODE == 1) ? blockIdx.x : blockIdx.y) * 128;
    const int n0 = ((MODE == 1) ? blockIdx.y : blockIdx.x) * 128;
    const u64 koff = (MODE == 1) ? (u64)blockIdx.z * (NPTS / KSPLIT) : 0;

    const half* Ap = A0 + (u64)m0 * LDA + koff;
    const half* Bp = (MODE == 1) ? (B0 + n0 + koff * TWO_P) : (B0 + (u64)n0 * TWO_P);

#define LOAD_STAGE(SB, KT)                                                     \
    {                                                                          \
        _Pragma("unroll")                                                      \
        for (int p_ = 0; p_ < 2; p_++) {   /* A: 512 chunks of 16B */          \
            int q = tid + p_ * 256;                                            \
            int r = q >> 2, c = q & 3;                                         \
            u64 g = (u64)r * LDA + (u64)(KT) * 32 + c * 8;                     \
            cp_async16((SB) + r * 80 + c * 16, Ap + g);                        \
        }                                                                      \
        if (MODE == 1) {                   /* B: 32 rows x 256B, n-major */    \
            _Pragma("unroll")                                                  \
            for (int p_ = 0; p_ < 2; p_++) {                                   \
                int q = tid + p_ * 256;                                        \
                int r = q >> 4, c = q & 15;                                    \
                u64 g = (u64)((KT) * 32 + r) * TWO_P + c * 8;                  \
                cp_async16((SB) + 10240 + r * 272 + c * 16, Bp + g);           \
            }                                                                  \
        } else {                           /* B: 128 rows x 64B, K-contig */   \
            _Pragma("unroll")                                                  \
            for (int p_ = 0; p_ < 2; p_++) {                                   \
                int q = tid + p_ * 256;                                        \
                int r = q >> 2, c = q & 3;                                     \
                u64 g = (u64)r * TWO_P + (u64)(KT) * 32 + c * 8;               \
                cp_async16((SB) + 10240 + r * 80 + c * 16, Bp + g);            \
            }                                                                  \
        }                                                                      \
    }

    // per-lane ldmatrix offsets (layouts validated R8-R15)
    const uint32_t aoff = ((lane & 15) + wr * 64) * 80 + (lane >> 4) * 16;
    const uint32_t boff2x = ((lane & 7) + ((lane >> 4) & 1) * 8 + wc * 32) * 80
                          + ((lane >> 3) & 1) * 16;
    const uint32_t boff1x = (lane & 15) * 272 + wc * 64 + ((lane >> 4) & 1) * 16;

#define LDFRAGS(AH, BH, AB, K0)                                                \
    {                                                                          \
        _Pragma("unroll")                                                      \
        for (int mi = 0; mi < 4; mi++)                                         \
            ldm_x4(AH[mi], (AB) + aoff + mi * 1280 + (K0) * 2);                \
        _Pragma("unroll")                                                      \
        for (int ni = 0; ni < 4; ni += 2) {                                    \
            if (MODE == 1) {                                                   \
                ldm_x4t(&BH[ni][0], (AB) + 10240 + boff1x + ni * 16 + (K0) * 272); \
            } else {                                                           \
                ldm_x4(&BH[ni][0], (AB) + 10240 + boff2x + ni * 640 + (K0) * 2);   \
            }                                                                  \
        }                                                                      \
    }

#define DO_HMMA(AH, BH)                                                        \
    {                                                                          \
        _Pragma("unroll")                                                      \
        for (int mi = 0; mi < 4; mi++)                                         \
        _Pragma("unroll")                                                      \
        for (int ni = 0; ni < 4; ni++) mma16816(acc[mi][ni], AH[mi], BH[ni]);  \
    }

    float acc[4][4][4];
#pragma unroll
    for (int i = 0; i < 4; i++)
#pragma unroll
        for (int j = 0; j < 4; j++)
#pragma unroll
            for (int k = 0; k < 4; k++) acc[i][j][k] = 0.f;

    uint32_t ah0[4][4], bh0[4][2];
    uint32_t ah1[4][4], bh1[4][2];

    // prologue: stages 0..3 in flight
    LOAD_STAGE(s0 + 0 * STG, 0); CP_COMMIT();
    LOAD_STAGE(s0 + 1 * STG, 1); CP_COMMIT();
    LOAD_STAGE(s0 + 2 * STG, 2); CP_COMMIT();
    LOAD_STAGE(s0 + 3 * STG, 3); CP_COMMIT();
    CP_WAIT3();                      // stage 0 landed
    __syncthreads();
    LDFRAGS(ah0, bh0, s0, 0);        // frags(chunk 0, k0=0)

    int scur = 0;                    // stage ring index of chunk kt
    for (int kt = 0; kt < NK; kt++) {
        const uint32_t Ab = s0 + scur * STG;
        int snxt = scur + 1; if (snxt == 5) snxt = 0;
        const uint32_t Abn = s0 + snxt * STG;
        int spre = (scur == 0) ? 4 : scur - 1;   // (kt+4) % 5

        LDFRAGS(ah1, bh1, Ab, 16);               // LSU: frags(kt, k0=16)
        DO_HMMA(ah0, bh0);                       // tensor: frags(kt, k0=0)

        CP_WAIT2();                              // stage kt+1 landed
        __syncthreads();                         // all warps past stage spre reads
        if (kt + 4 < NK) LOAD_STAGE(s0 + spre * STG, kt + 4);
        CP_COMMIT();                             // always: group numbering invariant

        if (kt + 1 < NK) LDFRAGS(ah0, bh0, Abn, 0);   // frags(kt+1, 0)
        DO_HMMA(ah1, bh1);                       // frags(kt, k0=16)

        scur = snxt;
    }

    // ---- epilogue (fp32 out both modes) ----
    const int rbase = wr * 64 + (lane >> 2);
    const int cbase = wc * 32 + (lane & 3) * 2;
    const u64 ldc  = (MODE == 1) ? (u64)TWO_P : (u64)TWO_D;
    float* og = outF + (u64)m0 * ldc + n0
              + ((MODE == 1) ? (u64)blockIdx.z * ((u64)TWO_D * TWO_P) : 0);
#pragma unroll
    for (int mi = 0; mi < 4; mi++)
#pragma unroll
        for (int ni = 0; ni < 4; ni++)
#pragma unroll
            for (int hh = 0; hh < 2; hh++) {
                int r = rbase + mi * 16 + hh * 8;
                int c = cbase + ni * 8;
                *(float2*)&og[(u64)r * ldc + c] =
                    make_float2(acc[mi][ni][hh * 2 + 0], acc[mi][ni][hh * 2 + 1]);
            }
#undef LOAD_STAGE
#undef LDFRAGS
#undef DO_HMMA
}

// ---------------- split-K reduce -> fp16 C1T ----------------
__global__ void reduce_c1(const float* __restrict__ P, half* __restrict__ T)
{
    const u64 CH = (u64)TWO_D * TWO_P;
    u64 i = ((u64)blockIdx.x * 256 + threadIdx.x) * 2;
    float2 a0 = *(const float2*)&P[i];
    float2 a1 = *(const float2*)&P[CH + i];
    float2 a2 = *(const float2*)&P[2 * CH + i];
    float2 a3 = *(const float2*)&P[3 * CH + i];
    float v0 = (a0.x + a1.x) + (a2.x + a3.x);
    float v1 = (a0.y + a1.y) + (a2.y + a3.y);
    *(half2*)&T[i] = __halves2half2(__float2half_rn(v0), __float2half_rn(v1));
}

// ---------------- finalize (recomputes eA phases inline) ----------------
__global__ void finalize_kernel(float* __restrict__ G, const float* __restrict__ pts,
                                const float* __restrict__ W)
{
    __shared__ float red[256];
    int n = blockIdx.x, t = threadIdx.x;
    u64 base = (u64)n * TWO_D;
    float x0 = pts[3*n+0]*20.f, x1 = pts[3*n+1]*20.f, x2 = pts[3*n+2]*20.f;

    float re[2], im[2], acc = 0.f;
#pragma unroll
    for (int q = 0; q < 2; q++) {
        int j = t + q * 256;
        float ph = x0*W[j] + x1*W[DENC+j] + x2*W[2*DENC+j];
        float sA, cA; fast_sincos(ph, sA, cA);
        float Gc = G[base + j], Gs = G[base + DENC + j];
        float den = cA * cA + sA * sA;
        float r  = (Gc * cA + Gs * sA) / den;
        float ii = (Gs * cA - Gc * sA) / den;
        re[q] = r; im[q] = ii;
        acc += r * r + ii * ii;
    }
    red[t] = acc;
    __syncthreads();
#pragma unroll
    for (int s = 128; s > 0; s >>= 1) {
        if (t < s) red[t] += red[t + s];
        __syncthreads();
    }
    float scale = 22.62741699796952f / sqrtf(red[0]);   // sqrt(512)/nrm
#pragma unroll
    for (int q = 0; q < 2; q++) {
        int j = t + q * 256;
        G[base + j]        = re[q] * scale;
        G[base + DENC + j] = im[q] * scale;
    }
}

// ---------------------------------------------------------------------------
extern "C" void kernel_launch(void* const* d_in, const int* in_sizes, int n_in,
                              void* d_out, int out_size)
{
    const float* pts = (const float*)d_in[0];
    const float* A   = (const float*)d_in[1];
    const float* B   = (const float*)d_in[2];
    float* out = (float*)d_out;

    half *eB16, *eAT16, *C1T16;
    float *C1p;
    cudaGetSymbolAddress((void**)&eB16,  g_eB16);
    cudaGetSymbolAddress((void**)&eAT16, g_eAT16);
    cudaGetSymbolAddress((void**)&C1T16, g_C1T16);
    cudaGetSymbolAddress((void**)&C1p,   g_C1p);

    const int SMEM1 = 5 * (10240 + 8704);     // 94720
    const int SMEM2 = 5 * (10240 + 10240);    // 102400
    cudaFuncSetAttribute(gemm_mma<1>, cudaFuncAttributeMaxDynamicSharedMemorySize, SMEM1);
    cudaFuncSetAttribute(gemm_mma<2>, cudaFuncAttributeMaxDynamicSharedMemorySize, SMEM2);

    enc_eB <<<((u64)NPTS * PDIM) / 256, 256>>>(pts, B);
    enc_eAT<<<((u64)DENC * NPTS) / 256, 256>>>(pts, A);

    // GEMM1: C1p[z] = partial over K-quarter z of eAT16[d][n] * eB16[n][p]
    // grid x = d-tile (8, fastest) -> eB slabs shared in L2 across d-tiles
    gemm_mma<1><<<dim3(TWO_D / 128, TWO_P / 128, KSPLIT), 256, SMEM1>>>(
        eAT16, eB16, C1p);
    reduce_c1<<<(TWO_D * TWO_P) / 512, 256>>>(C1p, C1T16);

    // GEMM2: G[n][d] = sum_p eB16[n][p] * C1T16[d][p]
    gemm_mma<2><<<dim3(TWO_D / 128, NPTS / 128), 256, SMEM2>>>(
        eB16, C1T16, out);

    finalize_kernel<<<NPTS, 256>>>(out, pts, A);
}

// round 17
// speedup vs baseline: 2.4900x; 1.1670x over previous
#include <cuda_runtime.h>
#include <cuda_fp16.h>
#include <math.h>
#include <stdint.h>

#define NPTS  65536
#define DENC  512
#define PDIM  4096
#define TWO_D 1024
#define TWO_P 8192
#define KSPLIT 4

typedef unsigned long long u64;

// Scratch (allocation-free __device__ globals, ~784 MB total)
__device__ half  g_eB16[(u64)NPTS * TWO_P];   // 512 MB eB  fp16 [n][8192]
__device__ half  g_eAT16[(u64)TWO_D * NPTS];  // 128 MB eA^T fp16 [d][65536]
__device__ half  g_C1T16[(u64)TWO_D * TWO_P]; // 16 MB  C1^T fp16 [d][8192]
__device__ float g_C1p [(u64)KSPLIT * TWO_D * TWO_P];  // 128 MB split-K partials

// ---------------- PTX helpers (base sm_103 ISA only) ----------------
__device__ __forceinline__ uint32_t smem_u32(const void* p) {
    uint32_t a;
    asm("{ .reg .u64 t; cvta.to.shared.u64 t, %1; cvt.u32.u64 %0, t; }" : "=r"(a) : "l"(p));
    return a;
}
__device__ __forceinline__ void cp_async16(uint32_t dst, const void* src) {
    asm volatile("cp.async.cg.shared.global [%0], [%1], 16;" :: "r"(dst), "l"(src));
}
#define CP_COMMIT() asm volatile("cp.async.commit_group;" ::: "memory")
#define CP_WAIT3()  asm volatile("cp.async.wait_group 3;" ::: "memory")
#define CP_WAIT2()  asm volatile("cp.async.wait_group 2;" ::: "memory")

__device__ __forceinline__ void ldm_x4(uint32_t* r, uint32_t a) {
    asm volatile("ldmatrix.sync.aligned.m8n8.x4.shared.b16 {%0,%1,%2,%3}, [%4];"
        : "=r"(r[0]), "=r"(r[1]), "=r"(r[2]), "=r"(r[3]) : "r"(a));
}
__device__ __forceinline__ void ldm_x4t(uint32_t* r, uint32_t a) {
    asm volatile("ldmatrix.sync.aligned.m8n8.x4.trans.shared.b16 {%0,%1,%2,%3}, [%4];"
        : "=r"(r[0]), "=r"(r[1]), "=r"(r[2]), "=r"(r[3]) : "r"(a));
}
__device__ __forceinline__ void mma16816(float* c, const uint32_t* a, const uint32_t* b) {
    asm volatile("mma.sync.aligned.m16n8k16.row.col.f32.f16.f16.f32 "
        "{%0,%1,%2,%3}, {%4,%5,%6,%7}, {%8,%9}, {%0,%1,%2,%3};"
        : "+f"(c[0]), "+f"(c[1]), "+f"(c[2]), "+f"(c[3])
        : "r"(a[0]), "r"(a[1]), "r"(a[2]), "r"(a[3]), "r"(b[0]), "r"(b[1]));
}

// ---------------- fast accurate sincos ----------------
__device__ __forceinline__ void fast_sincos(float x, float& s, float& c) {
    float kf = rintf(x * 0.636619772f);          // 2/pi
    int   q  = (int)kf;
    float r  = fmaf(kf, -1.57079637f, x);        // pi/2 hi, exact via fma
    r = fmaf(kf, 4.37113900e-8f, r);             // hi - pi/2 correction
    float sr = __sinf(r), cr = __cosf(r);
    bool  sw = q & 1;
    float s0 = sw ? cr : sr;
    float c0 = sw ? sr : cr;
    s = (q & 2) ? -s0 : s0;
    c = ((q + 1) & 2) ? -c0 : c0;
}

// ---------------- encode ----------------
// 2-wide: each thread computes 2 adjacent p, half2 stores.
__global__ void enc_eB(const float* __restrict__ pts, const float* __restrict__ W) {
    u64 idx = (u64)blockIdx.x * 256 + threadIdx.x;
    int p = (int)(idx & 2047) * 2;
    int n = (int)(idx >> 11);
    float x0 = pts[3*n+0]*20.f, x1 = pts[3*n+1]*20.f, x2 = pts[3*n+2]*20.f;
    float ph0 = x0*W[p]   + x1*W[PDIM+p]   + x2*W[2*PDIM+p];
    float ph1 = x0*W[p+1] + x1*W[PDIM+p+1] + x2*W[2*PDIM+p+1];
    float s0, c0, s1, c1;
    fast_sincos(ph0, s0, c0);
    fast_sincos(ph1, s1, c1);
    u64 b = (u64)n * TWO_P;
    *(half2*)&g_eB16[b + p] = __halves2half2(__float2half_rn(c0), __float2half_rn(c1));
    *(half2*)&g_eB16[b + PDIM + p] = __halves2half2(__float2half_rn(s0), __float2half_rn(s1));
}

__global__ void enc_eAT(const float* __restrict__ pts, const float* __restrict__ W) {
    u64 idx = (u64)blockIdx.x * 256 + threadIdx.x;
    int n = (int)(idx & 65535);
    int j = (int)(idx >> 16);        // 0..511
    float x0 = pts[3*n+0]*20.f, x1 = pts[3*n+1]*20.f, x2 = pts[3*n+2]*20.f;
    float ph = x0*W[j] + x1*W[DENC+j] + x2*W[2*DENC+j];
    float s, c; fast_sincos(ph, s, c);
    g_eAT16[(u64)j * NPTS + n]          = __float2half_rn(c);
    g_eAT16[(u64)(j+DENC) * NPTS + n]   = __float2half_rn(s);
}

// ---------------- mma.sync single-term fp16 GEMM, BK=64 ----------------
// D[m][q] = sum_k A[m][k]*B[q][k], fp32 acc, 1 HMMA term per k-step.
// MODE 1 (GEMM1): A = eAT [d][n], B = eB [n][p] n-major (ldmatrix.x4.trans),
//                 split-K x4 via blockIdx.z, fp32 partials.
// MODE 2 (GEMM2): A = eB [n][p], B = C1T [d][p] K-contig (ldmatrix.x4).
// BM=BN=128, BK=64 (4 k0-steps/chunk -> half the waits/barriers of BK=32),
// 5-stage cp.async ring, frag double-buffer. A rows: 128B data + 16B pad
// (pitch 144: 144k mod 128 distinct for k=0..7 -> conflict-free ldmatrix).
template<int MODE>
__global__ __launch_bounds__(256, 1)
void gemm_mma(const half* __restrict__ A0, const half* __restrict__ B0,
              float* __restrict__ outF)
{
    constexpr int  NK  = (MODE == 1) ? (NPTS / KSPLIT / 64) : (TWO_P / 64);
    constexpr u64  LDA = (MODE == 1) ? (u64)NPTS : (u64)TWO_P;
    constexpr int  ABYTES = 128 * 144;                       // 18432
    constexpr int  STG = (MODE == 1) ? (ABYTES + 64 * 272)   // 35840
                                     : (ABYTES + 128 * 144); // 36864

    extern __shared__ __align__(16) char smem[];
    const uint32_t s0 = smem_u32(smem);

    const int tid  = threadIdx.x;
    const int lane = tid & 31;
    const int wid  = tid >> 5;
    const int wr   = wid >> 2;        // 0..1  (m)
    const int wc   = wid & 3;         // 0..3  (n)

    const int m0 = ((MODE == 1) ? blockIdx.x : blockIdx.y) * 128;
    const int n0 = ((MODE == 1) ? blockIdx.y : blockIdx.x) * 128;
    const u64 koff = (MODE == 1) ? (u64)blockIdx.z * (NPTS / KSPLIT) : 0;

    const half* Ap = A0 + (u64)m0 * LDA + koff;
    const half* Bp = (MODE == 1) ? (B0 + n0 + koff * TWO_P) : (B0 + (u64)n0 * TWO_P);

#define LOAD_STAGE(SB, KT)                                                     \
    {                                                                          \
        _Pragma("unroll")                                                      \
        for (int p_ = 0; p_ < 4; p_++) {   /* A: 1024 chunks of 16B */         \
            int q = tid + p_ * 256;                                            \
            int r = q >> 3, c = q & 7;                                         \
            u64 g = (u64)r * LDA + (u64)(KT) * 64 + c * 8;                     \
            cp_async16((SB) + r * 144 + c * 16, Ap + g);                       \
        }                                                                      \
        if (MODE == 1) {                   /* B: 64 rows x 256B, n-major */    \
            _Pragma("unroll")                                                  \
            for (int p_ = 0; p_ < 4; p_++) {                                   \
                int q = tid + p_ * 256;                                        \
                int r = q >> 4, c = q & 15;                                    \
                u64 g = (u64)((KT) * 64 + r) * TWO_P + c * 8;                  \
                cp_async16((SB) + ABYTES + r * 272 + c * 16, Bp + g);          \
            }                                                                  \
        } else {                           /* B: 128 rows x 128B, K-contig */  \
            _Pragma("unroll")                                                  \
            for (int p_ = 0; p_ < 4; p_++) {                                   \
                int q = tid + p_ * 256;                                        \
                int r = q >> 3, c = q & 7;                                     \
                u64 g = (u64)r * TWO_P + (u64)(KT) * 64 + c * 8;               \
                cp_async16((SB) + ABYTES + r * 144 + c * 16, Bp + g);          \
            }                                                                  \
        }                                                                      \
    }

    // per-lane ldmatrix offsets (same structure as validated pitch-80 layout)
    const uint32_t aoff = ((lane & 15) + wr * 64) * 144 + (lane >> 4) * 16;
    const uint32_t boff2x = ((lane & 7) + ((lane >> 4) & 1) * 8 + wc * 32) * 144
                          + ((lane >> 3) & 1) * 16;
    const uint32_t boff1x = (lane & 15) * 272 + wc * 64 + ((lane >> 4) & 1) * 16;

#define LDFRAGS(AH, BH, AB, K0)                                                \
    {                                                                          \
        _Pragma("unroll")                                                      \
        for (int mi = 0; mi < 4; mi++)                                         \
            ldm_x4(AH[mi], (AB) + aoff + mi * 2304 + (K0) * 2);                \
        _Pragma("unroll")                                                      \
        for (int ni = 0; ni < 4; ni += 2) {                                    \
            if (MODE == 1) {                                                   \
                ldm_x4t(&BH[ni][0], (AB) + ABYTES + boff1x + ni * 16 + (K0) * 272); \
            } else {                                                           \
                ldm_x4(&BH[ni][0], (AB) + ABYTES + boff2x + ni * 1152 + (K0) * 2);  \
            }                                                                  \
        }                                                                      \
    }

#define DO_HMMA(AH, BH)                                                        \
    {                                                                          \
        _Pragma("unroll")                                                      \
        for (int mi = 0; mi < 4; mi++)                                         \
        _Pragma("unroll")                                                      \
        for (int ni = 0; ni < 4; ni++) mma16816(acc[mi][ni], AH[mi], BH[ni]);  \
    }

    float acc[4][4][4];
#pragma unroll
    for (int i = 0; i < 4; i++)
#pragma unroll
        for (int j = 0; j < 4; j++)
#pragma unroll
            for (int k = 0; k < 4; k++) acc[i][j][k] = 0.f;

    uint32_t ah0[4][4], bh0[4][2];
    uint32_t ah1[4][4], bh1[4][2];

    // prologue: stages 0..3 in flight
    LOAD_STAGE(s0 + 0 * STG, 0); CP_COMMIT();
    LOAD_STAGE(s0 + 1 * STG, 1); CP_COMMIT();
    LOAD_STAGE(s0 + 2 * STG, 2); CP_COMMIT();
    LOAD_STAGE(s0 + 3 * STG, 3); CP_COMMIT();
    CP_WAIT3();                      // stage 0 landed
    __syncthreads();
    LDFRAGS(ah0, bh0, s0, 0);        // frags(chunk 0, k0=0)

    int scur = 0;                    // stage ring index of chunk kt
    for (int kt = 0; kt < NK; kt++) {
        const uint32_t Ab = s0 + scur * STG;
        int snxt = scur + 1; if (snxt == 5) snxt = 0;
        const uint32_t Abn = s0 + snxt * STG;
        int spre = (scur == 0) ? 4 : scur - 1;   // (kt+4) % 5

        LDFRAGS(ah1, bh1, Ab, 16);               // frags(kt, 16)
        DO_HMMA(ah0, bh0);                       // (kt, 0)
        LDFRAGS(ah0, bh0, Ab, 32);               // frags(kt, 32)
        DO_HMMA(ah1, bh1);                       // (kt, 16)
        LDFRAGS(ah1, bh1, Ab, 48);               // frags(kt, 48)
        DO_HMMA(ah0, bh0);                       // (kt, 32)

        CP_WAIT2();                              // stage kt+1 landed
        __syncthreads();                         // all warps past stage spre reads
        if (kt + 4 < NK) LOAD_STAGE(s0 + spre * STG, kt + 4);
        CP_COMMIT();                             // always: group numbering invariant

        if (kt + 1 < NK) LDFRAGS(ah0, bh0, Abn, 0);   // frags(kt+1, 0)
        DO_HMMA(ah1, bh1);                       // (kt, 48)

        scur = snxt;
    }

    // ---- epilogue (fp32 out both modes) ----
    const int rbase = wr * 64 + (lane >> 2);
    const int cbase = wc * 32 + (lane & 3) * 2;
    const u64 ldc  = (MODE == 1) ? (u64)TWO_P : (u64)TWO_D;
    float* og = outF + (u64)m0 * ldc + n0
              + ((MODE == 1) ? (u64)blockIdx.z * ((u64)TWO_D * TWO_P) : 0);
#pragma unroll
    for (int mi = 0; mi < 4; mi++)
#pragma unroll
        for (int ni = 0; ni < 4; ni++)
#pragma unroll
            for (int hh = 0; hh < 2; hh++) {
                int r = rbase + mi * 16 + hh * 8;
                int c = cbase + ni * 8;
                *(float2*)&og[(u64)r * ldc + c] =
                    make_float2(acc[mi][ni][hh * 2 + 0], acc[mi][ni][hh * 2 + 1]);
            }
#undef LOAD_STAGE
#undef LDFRAGS
#undef DO_HMMA
}

// ---------------- split-K reduce -> fp16 C1T ----------------
__global__ void reduce_c1(const float* __restrict__ P, half* __restrict__ T)
{
    const u64 CH = (u64)TWO_D * TWO_P;
    u64 i = ((u64)blockIdx.x * 256 + threadIdx.x) * 2;
    float2 a0 = *(const float2*)&P[i];
    float2 a1 = *(const float2*)&P[CH + i];
    float2 a2 = *(const float2*)&P[2 * CH + i];
    float2 a3 = *(const float2*)&P[3 * CH + i];
    float v0 = (a0.x + a1.x) + (a2.x + a3.x);
    float v1 = (a0.y + a1.y) + (a2.y + a3.y);
    *(half2*)&T[i] = __halves2half2(__float2half_rn(v0), __float2half_rn(v1));
}

// ---------------- finalize (recomputes eA phases inline) ----------------
__global__ void finalize_kernel(float* __restrict__ G, const float* __restrict__ pts,
                                const float* __restrict__ W)
{
    __shared__ float red[256];
    int n = blockIdx.x, t = threadIdx.x;
    u64 base = (u64)n * TWO_D;
    float x0 = pts[3*n+0]*20.f, x1 = pts[3*n+1]*20.f, x2 = pts[3*n+2]*20.f;

    float re[2], im[2], acc = 0.f;
#pragma unroll
    for (int q = 0; q < 2; q++) {
        int j = t + q * 256;
        float ph = x0*W[j] + x1*W[DENC+j] + x2*W[2*DENC+j];
        float sA, cA; fast_sincos(ph, sA, cA);
        float Gc = G[base + j], Gs = G[base + DENC + j];
        float den = cA * cA + sA * sA;
        float r  = (Gc * cA + Gs * sA) / den;
        float ii = (Gs * cA - Gc * sA) / den;
        re[q] = r; im[q] = ii;
        acc += r * r + ii * ii;
    }
    red[t] = acc;
    __syncthreads();
#pragma unroll
    for (int s = 128; s > 0; s >>= 1) {
        if (t < s) red[t] += red[t + s];
        __syncthreads();
    }
    float scale = 22.62741699796952f / sqrtf(red[0]);   // sqrt(512)/nrm
#pragma unroll
    for (int q = 0; q < 2; q++) {
        int j = t + q * 256;
        G[base + j]        = re[q] * scale;
        G[base + DENC + j] = im[q] * scale;
    }
}

// ---------------------------------------------------------------------------
extern "C" void kernel_launch(void* const* d_in, const int* in_sizes, int n_in,
                              void* d_out, int out_size)
{
    const float* pts = (const float*)d_in[0];
    const float* A   = (const float*)d_in[1];
    const float* B   = (const float*)d_in[2];
    float* out = (float*)d_out;

    half *eB16, *eAT16, *C1T16;
    float *C1p;
    cudaGetSymbolAddress((void**)&eB16,  g_eB16);
    cudaGetSymbolAddress((void**)&eAT16, g_eAT16);
    cudaGetSymbolAddress((void**)&C1T16, g_C1T16);
    cudaGetSymbolAddress((void**)&C1p,   g_C1p);

    const int SMEM1 = 5 * (128 * 144 + 64 * 272);     // 179200
    const int SMEM2 = 5 * (128 * 144 + 128 * 144);    // 184320
    cudaFuncSetAttribute(gemm_mma<1>, cudaFuncAttributeMaxDynamicSharedMemorySize, SMEM1);
    cudaFuncSetAttribute(gemm_mma<2>, cudaFuncAttributeMaxDynamicSharedMemorySize, SMEM2);

    enc_eB <<<((u64)NPTS * PDIM) / 512, 256>>>(pts, B);
    enc_eAT<<<((u64)DENC * NPTS) / 256, 256>>>(pts, A);

    // GEMM1: C1p[z] = partial over K-quarter z of eAT16[d][n] * eB16[n][p]
    gemm_mma<1><<<dim3(TWO_D / 128, TWO_P / 128, KSPLIT), 256, SMEM1>>>(
        eAT16, eB16, C1p);
    reduce_c1<<<(TWO_D * TWO_P) / 512, 256>>>(C1p, C1T16);

    // GEMM2: G[n][d] = sum_p eB16[n][p] * C1T16[d][p]
    gemm_mma<2><<<dim3(TWO_D / 128, NPTS / 128), 256, SMEM2>>>(
        eB16, C1T16, out);

    finalize_kernel<<<NPTS, 256>>>(out, pts, A);
}